// round 13
// baseline (speedup 1.0000x reference)
#include <cuda_runtime.h>

#define G_   1024
#define N_   65536
#define D_   128
#define E_   400000

// Scratch (device globals — no allocations allowed)
__device__ __align__(16) float g_A[G_ * 128];      // graph_and_focus @ W1[0:384] + b1 (64 scorer | 64 type cols)
__device__ __align__(16) float g_C[N_ * 128];      // node @ W1[384:512] + A[n2g[node]] (fused per-node table)
__device__ float g_cstop[64];                      // no_more_edges_rep @ scorer_W1[384:516]

// packed f32x2 helpers (full-rate FMA pipe; scalar 3-reg FFMA is half-rate)
__device__ __forceinline__ unsigned long long fma2(unsigned long long a, unsigned long long b,
                                                   unsigned long long c) {
    unsigned long long d;
    asm("fma.rn.f32x2 %0, %1, %2, %3;" : "=l"(d) : "l"(a), "l"(b), "l"(c));
    return d;
}
__device__ __forceinline__ unsigned long long pack2(float lo, float hi) {
    unsigned long long d;
    asm("mov.b64 %0, {%1, %2};" : "=l"(d) : "f"(lo), "f"(hi));
    return d;
}
__device__ __forceinline__ void unpack2(unsigned long long v, float& lo, float& hi) {
    asm("mov.b64 {%0, %1}, %2;" : "=f"(lo), "=f"(hi) : "l"(v));
}

// ---------------------------------------------------------------------------
// kP: cstop (K-split 4 ways). 1 block x 256 threads.
// ---------------------------------------------------------------------------
__global__ void kP(const float* __restrict__ no_more, const float* __restrict__ sW1) {
    __shared__ float part[4][64];
    int tid = threadIdx.x;
    int j = tid & 63, s = tid >> 6;
    float sum = 0.f;
#pragma unroll 3
    for (int k = s * 33; k < s * 33 + 33; k++)
        sum += no_more[k] * sW1[(384 + k) * 64 + j];
    part[s][j] = sum;
    __syncthreads();
    if (tid < 64)
        g_cstop[tid] = part[0][tid] + part[1][tid] + part[2][tid] + part[3][tid];
}

// ---------------------------------------------------------------------------
// kA v2: 4 graphs/block x 256 blocks (1024 warps, 2x R8's occupancy).
//     A[g][j] = [imr|pgr|focus] @ W1[0:384] + b1 ; stop logits inline.
//     (validated correct in R12's aborted run: output 0 passed)
// ---------------------------------------------------------------------------
__global__ void kA(const float* __restrict__ imr, const float* __restrict__ pgr,
                   const float* __restrict__ nodes, const int* __restrict__ focus,
                   const float* __restrict__ sW1, const float* __restrict__ sb1,
                   const float* __restrict__ tW1, const float* __restrict__ tb1,
                   const float* __restrict__ sW2, const float* __restrict__ sb2,
                   float* __restrict__ out) {
    __shared__ float xs[4][384];
    __shared__ float sred[4][2];
    int j = threadIdx.x;
    int g0 = blockIdx.x * 4;
#pragma unroll
    for (int r = 0; r < 4; r++) {
        int g = g0 + r;
        xs[r][j]       = imr[g * 128 + j];
        xs[r][128 + j] = pgr[g * 128 + j];
        xs[r][256 + j] = nodes[(size_t)focus[g] * 128 + j];
    }
    __syncthreads();
    bool isS = (j < 64);
    float bias = isS ? sb1[j] : tb1[j - 64];
    const float* W = isS ? (sW1 + j) : (tW1 + (j - 64));
    float acc[4];
#pragma unroll
    for (int r = 0; r < 4; r++) acc[r] = bias;
#pragma unroll 8
    for (int k = 0; k < 384; k++) {
        float w = W[k * 64];
#pragma unroll
        for (int r = 0; r < 4; r++) acc[r] = fmaf(xs[r][k], w, acc[r]);
    }
#pragma unroll
    for (int r = 0; r < 4; r++) g_A[(size_t)(g0 + r) * 128 + j] = acc[r];

    float ws2 = isS ? sW2[j] : 0.f;
    float cst = isS ? g_cstop[j] : 0.f;
#pragma unroll
    for (int r = 0; r < 4; r++) {
        float pv = isS ? fmaxf(acc[r] + cst, 0.f) * ws2 : 0.f;
#pragma unroll
        for (int o = 16; o >= 1; o >>= 1) pv += __shfl_xor_sync(0xffffffffu, pv, o);
        if ((j & 31) == 0 && isS) sred[r][j >> 5] = pv;
    }
    __syncthreads();
    if (j < 4) out[E_ + g0 + j] = sred[j][0] + sred[j][1] + sb2[0];
}

// ---------------------------------------------------------------------------
// kB (R9 v2, measured-best ~75us): 512 blocks x 512 threads, tile 128x128,
//     thread tile 8 rows x 4 cols, row-pair f32x2 accumulators, static smem.
// ---------------------------------------------------------------------------
__global__ __launch_bounds__(512, 2) void kB(const float* __restrict__ nodes,
                                             const float* __restrict__ sW1,
                                             const float* __restrict__ tW1,
                                             const int* __restrict__ n2g) {
    __shared__ float xs[32][132];   // [k][r] transposed, padded
    __shared__ float sw[32][128];   // [k][j] combined cols
    int tid = threadIdx.x;
    int tx = tid & 31, ty = tid >> 5;
    int c0 = tx * 4, r0 = ty * 8;
    int row0 = blockIdx.x * 128;

    unsigned long long acc[4][4];   // [row-pair][col]
#pragma unroll
    for (int i = 0; i < 4; i++)
#pragma unroll
        for (int j = 0; j < 4; j++) acc[i][j] = 0ull;

    for (int kc = 0; kc < 128; kc += 32) {
        for (int i = tid; i < 32 * 128; i += 512) {
            int k = i >> 7, j = i & 127;
            sw[k][j] = (j < 64) ? sW1[(384 + kc + k) * 64 + j]
                                : tW1[(384 + kc + k) * 64 + (j - 64)];
        }
        for (int f = tid; f < 1024; f += 512) {
            int r = f >> 3, kq = (f & 7) << 2;
            float4 v = *(const float4*)(nodes + (size_t)(row0 + r) * 128 + kc + kq);
            xs[kq + 0][r] = v.x; xs[kq + 1][r] = v.y;
            xs[kq + 2][r] = v.z; xs[kq + 3][r] = v.w;
        }
        __syncthreads();
#pragma unroll 8
        for (int k = 0; k < 32; k++) {
            const unsigned long long* xp = (const unsigned long long*)&xs[k][r0];
            unsigned long long x0 = xp[0], x1 = xp[1], x2 = xp[2], x3 = xp[3];
            float4 w = *(const float4*)&sw[k][c0];
            unsigned long long w0 = pack2(w.x, w.x), w1 = pack2(w.y, w.y);
            unsigned long long w2 = pack2(w.z, w.z), w3 = pack2(w.w, w.w);
            acc[0][0] = fma2(x0, w0, acc[0][0]); acc[0][1] = fma2(x0, w1, acc[0][1]);
            acc[0][2] = fma2(x0, w2, acc[0][2]); acc[0][3] = fma2(x0, w3, acc[0][3]);
            acc[1][0] = fma2(x1, w0, acc[1][0]); acc[1][1] = fma2(x1, w1, acc[1][1]);
            acc[1][2] = fma2(x1, w2, acc[1][2]); acc[1][3] = fma2(x1, w3, acc[1][3]);
            acc[2][0] = fma2(x2, w0, acc[2][0]); acc[2][1] = fma2(x2, w1, acc[2][1]);
            acc[2][2] = fma2(x2, w2, acc[2][2]); acc[2][3] = fma2(x2, w3, acc[2][3]);
            acc[3][0] = fma2(x3, w0, acc[3][0]); acc[3][1] = fma2(x3, w1, acc[3][1]);
            acc[3][2] = fma2(x3, w2, acc[3][2]); acc[3][3] = fma2(x3, w3, acc[3][3]);
        }
        __syncthreads();
    }
    // epilogue: unpack, add A[n2g[row]] (n2g sorted -> near-sequential), store
#pragma unroll
    for (int i = 0; i < 4; i++) {
        float lo[4], hi[4];
#pragma unroll
        for (int j = 0; j < 4; j++) unpack2(acc[i][j], lo[j], hi[j]);
        int rowA = row0 + r0 + 2 * i;
        int gA = n2g[rowA], gB = n2g[rowA + 1];
        float4 a0 = *(const float4*)(g_A + (size_t)gA * 128 + c0);
        float4 b0 = *(const float4*)(g_A + (size_t)gB * 128 + c0);
        *(float4*)(g_C + (size_t)rowA * 128 + c0) =
            make_float4(lo[0] + a0.x, lo[1] + a0.y, lo[2] + a0.z, lo[3] + a0.w);
        *(float4*)(g_C + (size_t)(rowA + 1) * 128 + c0) =
            make_float4(hi[0] + b0.x, hi[1] + b0.y, hi[2] + b0.z, hi[3] + b0.w);
    }
}

// ---------------------------------------------------------------------------
// kE v3b: 1 edge per warp, lane owns 4 combined cols; h-chain in packed f32x2.
//     FIX vs v3: C gather uses cb = cbase + 64 for type lanes (v3 read the
//     scorer half of C for type lanes -> output-1 rel_err 1.0).
// ---------------------------------------------------------------------------
__global__ __launch_bounds__(256) void kE(const int* __restrict__ targets,
                   const float4* __restrict__ feats4,
                   const float* __restrict__ sW1, const float* __restrict__ tW1,
                   const float* __restrict__ sW2, const float* __restrict__ sb2,
                   const float* __restrict__ tW2, const float* __restrict__ tb2,
                   const float* __restrict__ dist_table,
                   float* __restrict__ out) {
    __shared__ float sdt[10];
    if (threadIdx.x < 10) sdt[threadIdx.x] = dist_table[threadIdx.x];
    __syncthreads();

    int lane = threadIdx.x & 31;
    bool isS = (lane < 16);
    int cbase = (lane & 15) * 4;            // col base within 64-wide W1 arrays
    int cb = cbase + (isS ? 0 : 64);        // col base within combined 128-wide C
    const float* W1 = isS ? sW1 : tW1;
    // packed first-layer weights: pair (col, col+1) and (col+2, col+3)
    ulonglong2 w512p = *(const ulonglong2*)(W1 + 512 * 64 + cbase);
    ulonglong2 w513p = *(const ulonglong2*)(W1 + 513 * 64 + cbase);
    ulonglong2 w514p = *(const ulonglong2*)(W1 + 514 * 64 + cbase);
    ulonglong2 w515p = *(const ulonglong2*)(W1 + 515 * 64 + cbase);
    float4 u0, u1, u2;
    if (isS) {
        u0 = *(const float4*)(sW2 + cbase);
        u1 = make_float4(0.f, 0.f, 0.f, 0.f);
        u2 = u1;
    } else {
        u0.x = tW2[(cbase + 0) * 3]; u0.y = tW2[(cbase + 1) * 3];
        u0.z = tW2[(cbase + 2) * 3]; u0.w = tW2[(cbase + 3) * 3];
        u1.x = tW2[(cbase + 0) * 3 + 1]; u1.y = tW2[(cbase + 1) * 3 + 1];
        u1.z = tW2[(cbase + 2) * 3 + 1]; u1.w = tW2[(cbase + 3) * 3 + 1];
        u2.x = tW2[(cbase + 0) * 3 + 2]; u2.y = tW2[(cbase + 1) * 3 + 2];
        u2.z = tW2[(cbase + 2) * 3 + 2]; u2.w = tW2[(cbase + 3) * 3 + 2];
    }
    float sb2v = sb2[0];
    float tb0 = tb2[0], tb1v = tb2[1], tb2v = tb2[2];
    float* outT = out + (E_ + G_);

    int gw = (blockIdx.x * blockDim.x + threadIdx.x) >> 5;
    int nw = (gridDim.x * blockDim.x) >> 5;

    int e = gw;
    float4 f;
    ulonglong2 c;
    if (e < E_) {
        int t = targets[e];
        f = feats4[e];
        c = *(const ulonglong2*)(g_C + (size_t)t * 128 + cb);
    }
    while (e < E_) {
        int e2 = e + nw;
        float4 f2;
        ulonglong2 c2;
        if (e2 < E_) {
            int t2 = targets[e2];
            f2 = feats4[e2];
            c2 = *(const ulonglong2*)(g_C + (size_t)t2 * 128 + cb);
        }
        float dv = sdt[(int)fminf(f.x, 9.0f)];
        unsigned long long dv2 = pack2(dv, dv);
        unsigned long long fy2 = pack2(f.y, f.y);
        unsigned long long fz2 = pack2(f.z, f.z);
        unsigned long long fw2 = pack2(f.w, f.w);
        unsigned long long h01 =
            fma2(dv2, w512p.x, fma2(fy2, w513p.x, fma2(fz2, w514p.x, fma2(fw2, w515p.x, c.x))));
        unsigned long long h23 =
            fma2(dv2, w512p.y, fma2(fy2, w513p.y, fma2(fz2, w514p.y, fma2(fw2, w515p.y, c.y))));
        float hx, hy, hz, hw;
        unpack2(h01, hx, hy);
        unpack2(h23, hz, hw);
        hx = fmaxf(hx, 0.f); hy = fmaxf(hy, 0.f);
        hz = fmaxf(hz, 0.f); hw = fmaxf(hw, 0.f);
        float v0 = fmaf(hx, u0.x, fmaf(hy, u0.y, fmaf(hz, u0.z, hw * u0.w)));
        float v1 = fmaf(hx, u1.x, fmaf(hy, u1.y, fmaf(hz, u1.z, hw * u1.w)));
        float v2 = fmaf(hx, u2.x, fmaf(hy, u2.y, fmaf(hz, u2.z, hw * u2.w)));
        float p = isS ? v0 : v1;
        float q = __shfl_xor_sync(0xffffffffu, v0, 16);
        q = isS ? q : v2;
#pragma unroll
        for (int o = 1; o <= 8; o <<= 1) {
            p += __shfl_xor_sync(0xffffffffu, p, o);
            q += __shfl_xor_sync(0xffffffffu, q, o);
        }
        if (lane == 0) {
            out[e] = p + sb2v;          // scorer logit
            outT[3 * e] = q + tb0;      // type logit 0
        }
        if (lane == 16) {
            outT[3 * e + 1] = p + tb1v; // type logit 1
            outT[3 * e + 2] = q + tb2v; // type logit 2
        }
        e = e2; f = f2; c = c2;
    }
}

// ---------------------------------------------------------------------------
extern "C" void kernel_launch(void* const* d_in, const int* in_sizes, int n_in,
                              void* d_out, int out_size) {
    const float* imr     = (const float*)d_in[0];
    const float* pgr     = (const float*)d_in[1];
    const float* nodes   = (const float*)d_in[2];
    const int*   focus   = (const int*)d_in[3];
    const int*   n2g     = (const int*)d_in[4];
    const int*   targets = (const int*)d_in[5];
    const float* feats   = (const float*)d_in[6];
    int p = 7;
    if (p < n_in && in_sizes[p] == 1) p++;  // skip num_graphs_in_batch scalar if present
    const float* dist_table = (const float*)d_in[p++];  // [10]
    const float* no_more    = (const float*)d_in[p++];  // [132]
    const float* sW1 = (const float*)d_in[p++];         // [516,64]
    const float* sb1 = (const float*)d_in[p++];         // [64]
    const float* sW2 = (const float*)d_in[p++];         // [64]
    const float* sb2 = (const float*)d_in[p++];         // [1]
    const float* tW1 = (const float*)d_in[p++];         // [516,64]
    const float* tb1 = (const float*)d_in[p++];         // [64]
    const float* tW2 = (const float*)d_in[p++];         // [64,3]
    const float* tb2 = (const float*)d_in[p++];         // [3]
    float* out = (float*)d_out;

    kP<<<1, 256>>>(no_more, sW1);
    kA<<<G_ / 4, 128>>>(imr, pgr, nodes, focus, sW1, sb1, tW1, tb1, sW2, sb2, out);
    kB<<<N_ / 128, 512>>>(nodes, sW1, tW1, n2g);
    kE<<<1184, 256>>>(targets, (const float4*)feats, sW1, tW1, sW2, sb2, tW2, tb2,
                      dist_table, out);
}

// round 14
// speedup vs baseline: 1.0580x; 1.0580x over previous
#include <cuda_runtime.h>

#define G_   1024
#define N_   65536
#define D_   128
#define E_   400000

// Scratch (device globals — no allocations allowed)
__device__ __align__(16) float g_A[G_ * 128];      // graph_and_focus @ W1[0:384] + b1 (64 scorer | 64 type cols)
__device__ __align__(16) float g_C[N_ * 128];      // node @ W1[384:512] + A[n2g[node]] (fused per-node table)
__device__ float g_cstop[64];                      // no_more_edges_rep @ scorer_W1[384:516]

// packed f32x2 helpers (full-rate FMA pipe; scalar 3-reg FFMA is half-rate)
__device__ __forceinline__ unsigned long long fma2(unsigned long long a, unsigned long long b,
                                                   unsigned long long c) {
    unsigned long long d;
    asm("fma.rn.f32x2 %0, %1, %2, %3;" : "=l"(d) : "l"(a), "l"(b), "l"(c));
    return d;
}
__device__ __forceinline__ unsigned long long pack2(float lo, float hi) {
    unsigned long long d;
    asm("mov.b64 %0, {%1, %2};" : "=l"(d) : "f"(lo), "f"(hi));
    return d;
}
__device__ __forceinline__ void unpack2(unsigned long long v, float& lo, float& hi) {
    asm("mov.b64 {%0, %1}, %2;" : "=f"(lo), "=f"(hi) : "l"(v));
}

// ---------------------------------------------------------------------------
// kP: cstop (K-split 4 ways). 1 block x 256 threads.
// ---------------------------------------------------------------------------
__global__ void kP(const float* __restrict__ no_more, const float* __restrict__ sW1) {
    __shared__ float part[4][64];
    int tid = threadIdx.x;
    int j = tid & 63, s = tid >> 6;
    float sum = 0.f;
#pragma unroll 3
    for (int k = s * 33; k < s * 33 + 33; k++)
        sum += no_more[k] * sW1[(384 + k) * 64 + j];
    part[s][j] = sum;
    __syncthreads();
    if (tid < 64)
        g_cstop[tid] = part[0][tid] + part[1][tid] + part[2][tid] + part[3][tid];
}

// ---------------------------------------------------------------------------
// kA v2: 4 graphs/block x 256 blocks. A[g][j] = [imr|pgr|focus] @ W1[0:384]
//     + b1 ; stop logits inline. (validated R12/R13)
// ---------------------------------------------------------------------------
__global__ void kA(const float* __restrict__ imr, const float* __restrict__ pgr,
                   const float* __restrict__ nodes, const int* __restrict__ focus,
                   const float* __restrict__ sW1, const float* __restrict__ sb1,
                   const float* __restrict__ tW1, const float* __restrict__ tb1,
                   const float* __restrict__ sW2, const float* __restrict__ sb2,
                   float* __restrict__ out) {
    __shared__ float xs[4][384];
    __shared__ float sred[4][2];
    int j = threadIdx.x;
    int g0 = blockIdx.x * 4;
#pragma unroll
    for (int r = 0; r < 4; r++) {
        int g = g0 + r;
        xs[r][j]       = imr[g * 128 + j];
        xs[r][128 + j] = pgr[g * 128 + j];
        xs[r][256 + j] = nodes[(size_t)focus[g] * 128 + j];
    }
    __syncthreads();
    bool isS = (j < 64);
    float bias = isS ? sb1[j] : tb1[j - 64];
    const float* W = isS ? (sW1 + j) : (tW1 + (j - 64));
    float acc[4];
#pragma unroll
    for (int r = 0; r < 4; r++) acc[r] = bias;
#pragma unroll 8
    for (int k = 0; k < 384; k++) {
        float w = W[k * 64];
#pragma unroll
        for (int r = 0; r < 4; r++) acc[r] = fmaf(xs[r][k], w, acc[r]);
    }
#pragma unroll
    for (int r = 0; r < 4; r++) g_A[(size_t)(g0 + r) * 128 + j] = acc[r];

    float ws2 = isS ? sW2[j] : 0.f;
    float cst = isS ? g_cstop[j] : 0.f;
#pragma unroll
    for (int r = 0; r < 4; r++) {
        float pv = isS ? fmaxf(acc[r] + cst, 0.f) * ws2 : 0.f;
#pragma unroll
        for (int o = 16; o >= 1; o >>= 1) pv += __shfl_xor_sync(0xffffffffu, pv, o);
        if ((j & 31) == 0 && isS) sred[r][j >> 5] = pv;
    }
    __syncthreads();
    if (j < 4) out[E_ + g0 + j] = sred[j][0] + sred[j][1] + sb2[0];
}

// ---------------------------------------------------------------------------
// kB (R9 v2, measured-best ~75us): 512 blocks x 512 threads, tile 128x128,
//     thread tile 8 rows x 4 cols, row-pair f32x2 accumulators, static smem.
// ---------------------------------------------------------------------------
__global__ __launch_bounds__(512, 2) void kB(const float* __restrict__ nodes,
                                             const float* __restrict__ sW1,
                                             const float* __restrict__ tW1,
                                             const int* __restrict__ n2g) {
    __shared__ float xs[32][132];   // [k][r] transposed, padded
    __shared__ float sw[32][128];   // [k][j] combined cols
    int tid = threadIdx.x;
    int tx = tid & 31, ty = tid >> 5;
    int c0 = tx * 4, r0 = ty * 8;
    int row0 = blockIdx.x * 128;

    unsigned long long acc[4][4];   // [row-pair][col]
#pragma unroll
    for (int i = 0; i < 4; i++)
#pragma unroll
        for (int j = 0; j < 4; j++) acc[i][j] = 0ull;

    for (int kc = 0; kc < 128; kc += 32) {
        for (int i = tid; i < 32 * 128; i += 512) {
            int k = i >> 7, j = i & 127;
            sw[k][j] = (j < 64) ? sW1[(384 + kc + k) * 64 + j]
                                : tW1[(384 + kc + k) * 64 + (j - 64)];
        }
        for (int f = tid; f < 1024; f += 512) {
            int r = f >> 3, kq = (f & 7) << 2;
            float4 v = *(const float4*)(nodes + (size_t)(row0 + r) * 128 + kc + kq);
            xs[kq + 0][r] = v.x; xs[kq + 1][r] = v.y;
            xs[kq + 2][r] = v.z; xs[kq + 3][r] = v.w;
        }
        __syncthreads();
#pragma unroll 8
        for (int k = 0; k < 32; k++) {
            const unsigned long long* xp = (const unsigned long long*)&xs[k][r0];
            unsigned long long x0 = xp[0], x1 = xp[1], x2 = xp[2], x3 = xp[3];
            float4 w = *(const float4*)&sw[k][c0];
            unsigned long long w0 = pack2(w.x, w.x), w1 = pack2(w.y, w.y);
            unsigned long long w2 = pack2(w.z, w.z), w3 = pack2(w.w, w.w);
            acc[0][0] = fma2(x0, w0, acc[0][0]); acc[0][1] = fma2(x0, w1, acc[0][1]);
            acc[0][2] = fma2(x0, w2, acc[0][2]); acc[0][3] = fma2(x0, w3, acc[0][3]);
            acc[1][0] = fma2(x1, w0, acc[1][0]); acc[1][1] = fma2(x1, w1, acc[1][1]);
            acc[1][2] = fma2(x1, w2, acc[1][2]); acc[1][3] = fma2(x1, w3, acc[1][3]);
            acc[2][0] = fma2(x2, w0, acc[2][0]); acc[2][1] = fma2(x2, w1, acc[2][1]);
            acc[2][2] = fma2(x2, w2, acc[2][2]); acc[2][3] = fma2(x2, w3, acc[2][3]);
            acc[3][0] = fma2(x3, w0, acc[3][0]); acc[3][1] = fma2(x3, w1, acc[3][1]);
            acc[3][2] = fma2(x3, w2, acc[3][2]); acc[3][3] = fma2(x3, w3, acc[3][3]);
        }
        __syncthreads();
    }
    // epilogue: unpack, add A[n2g[row]] (n2g sorted -> near-sequential), store
#pragma unroll
    for (int i = 0; i < 4; i++) {
        float lo[4], hi[4];
#pragma unroll
        for (int j = 0; j < 4; j++) unpack2(acc[i][j], lo[j], hi[j]);
        int rowA = row0 + r0 + 2 * i;
        int gA = n2g[rowA], gB = n2g[rowA + 1];
        float4 a0 = *(const float4*)(g_A + (size_t)gA * 128 + c0);
        float4 b0 = *(const float4*)(g_A + (size_t)gB * 128 + c0);
        *(float4*)(g_C + (size_t)rowA * 128 + c0) =
            make_float4(lo[0] + a0.x, lo[1] + a0.y, lo[2] + a0.z, lo[3] + a0.w);
        *(float4*)(g_C + (size_t)(rowA + 1) * 128 + c0) =
            make_float4(hi[0] + b0.x, hi[1] + b0.y, hi[2] + b0.z, hi[3] + b0.w);
    }
}

// ---------------------------------------------------------------------------
// kE (R8/R9 exact, measured 74.0us twice): 1 edge per warp, lane owns 4
//     combined cols via float4 gather; scalar 4-chain FMA h; scalar dist;
//     1-deep prefetch of targets->C chain.
// ---------------------------------------------------------------------------
__global__ __launch_bounds__(256) void kE(const int* __restrict__ targets,
                   const float4* __restrict__ feats4,
                   const float* __restrict__ sW1, const float* __restrict__ tW1,
                   const float* __restrict__ sW2, const float* __restrict__ sb2,
                   const float* __restrict__ tW2, const float* __restrict__ tb2,
                   const float* __restrict__ dist_table,
                   float* __restrict__ out) {
    __shared__ float sdt[10];
    if (threadIdx.x < 10) sdt[threadIdx.x] = dist_table[threadIdx.x];
    __syncthreads();

    int lane = threadIdx.x & 31;
    bool isS = (lane < 16);
    int cbase = (lane & 15) * 4;
    const float* W1 = isS ? sW1 : tW1;
    float4 w512 = *(const float4*)(W1 + 512 * 64 + cbase);
    float4 w513 = *(const float4*)(W1 + 513 * 64 + cbase);
    float4 w514 = *(const float4*)(W1 + 514 * 64 + cbase);
    float4 w515 = *(const float4*)(W1 + 515 * 64 + cbase);
    float4 u0, u1, u2;
    if (isS) {
        u0 = *(const float4*)(sW2 + cbase);
        u1 = make_float4(0.f, 0.f, 0.f, 0.f);
        u2 = u1;
    } else {
        u0.x = tW2[(cbase + 0) * 3]; u0.y = tW2[(cbase + 1) * 3];
        u0.z = tW2[(cbase + 2) * 3]; u0.w = tW2[(cbase + 3) * 3];
        u1.x = tW2[(cbase + 0) * 3 + 1]; u1.y = tW2[(cbase + 1) * 3 + 1];
        u1.z = tW2[(cbase + 2) * 3 + 1]; u1.w = tW2[(cbase + 3) * 3 + 1];
        u2.x = tW2[(cbase + 0) * 3 + 2]; u2.y = tW2[(cbase + 1) * 3 + 2];
        u2.z = tW2[(cbase + 2) * 3 + 2]; u2.w = tW2[(cbase + 3) * 3 + 2];
    }
    float sb2v = sb2[0];
    float tb0 = tb2[0], tb1v = tb2[1], tb2v = tb2[2];
    const float4* C4 = (const float4*)g_C;
    float* outT = out + (E_ + G_);

    int gw = (blockIdx.x * blockDim.x + threadIdx.x) >> 5;
    int nw = (gridDim.x * blockDim.x) >> 5;

    int e = gw;
    float4 f, c;
    if (e < E_) {
        int t = targets[e];
        f = feats4[e];
        c = C4[(size_t)t * 32 + lane];
    }
    while (e < E_) {
        int e2 = e + nw;
        float4 f2, c2;
        if (e2 < E_) {
            int t2 = targets[e2];
            f2 = feats4[e2];
            c2 = C4[(size_t)t2 * 32 + lane];
        }
        float dv = sdt[(int)fminf(f.x, 9.0f)];
        float hx = fmaxf(fmaf(dv, w512.x, fmaf(f.y, w513.x, fmaf(f.z, w514.x, fmaf(f.w, w515.x, c.x)))), 0.f);
        float hy = fmaxf(fmaf(dv, w512.y, fmaf(f.y, w513.y, fmaf(f.z, w514.y, fmaf(f.w, w515.y, c.y)))), 0.f);
        float hz = fmaxf(fmaf(dv, w512.z, fmaf(f.y, w513.z, fmaf(f.z, w514.z, fmaf(f.w, w515.z, c.z)))), 0.f);
        float hw = fmaxf(fmaf(dv, w512.w, fmaf(f.y, w513.w, fmaf(f.z, w514.w, fmaf(f.w, w515.w, c.w)))), 0.f);
        float v0 = fmaf(hx, u0.x, fmaf(hy, u0.y, fmaf(hz, u0.z, hw * u0.w)));
        float v1 = fmaf(hx, u1.x, fmaf(hy, u1.y, fmaf(hz, u1.z, hw * u1.w)));
        float v2 = fmaf(hx, u2.x, fmaf(hy, u2.y, fmaf(hz, u2.z, hw * u2.w)));
        float p = isS ? v0 : v1;
        float q = __shfl_xor_sync(0xffffffffu, v0, 16);
        q = isS ? q : v2;
#pragma unroll
        for (int o = 1; o <= 8; o <<= 1) {
            p += __shfl_xor_sync(0xffffffffu, p, o);
            q += __shfl_xor_sync(0xffffffffu, q, o);
        }
        if (lane == 0) {
            out[e] = p + sb2v;          // scorer logit
            outT[3 * e] = q + tb0;      // type logit 0
        }
        if (lane == 16) {
            outT[3 * e + 1] = p + tb1v; // type logit 1
            outT[3 * e + 2] = q + tb2v; // type logit 2
        }
        e = e2; f = f2; c = c2;
    }
}

// ---------------------------------------------------------------------------
extern "C" void kernel_launch(void* const* d_in, const int* in_sizes, int n_in,
                              void* d_out, int out_size) {
    const float* imr     = (const float*)d_in[0];
    const float* pgr     = (const float*)d_in[1];
    const float* nodes   = (const float*)d_in[2];
    const int*   focus   = (const int*)d_in[3];
    const int*   n2g     = (const int*)d_in[4];
    const int*   targets = (const int*)d_in[5];
    const float* feats   = (const float*)d_in[6];
    int p = 7;
    if (p < n_in && in_sizes[p] == 1) p++;  // skip num_graphs_in_batch scalar if present
    const float* dist_table = (const float*)d_in[p++];  // [10]
    const float* no_more    = (const float*)d_in[p++];  // [132]
    const float* sW1 = (const float*)d_in[p++];         // [516,64]
    const float* sb1 = (const float*)d_in[p++];         // [64]
    const float* sW2 = (const float*)d_in[p++];         // [64]
    const float* sb2 = (const float*)d_in[p++];         // [1]
    const float* tW1 = (const float*)d_in[p++];         // [516,64]
    const float* tb1 = (const float*)d_in[p++];         // [64]
    const float* tW2 = (const float*)d_in[p++];         // [64,3]
    const float* tb2 = (const float*)d_in[p++];         // [3]
    float* out = (float*)d_out;

    kP<<<1, 256>>>(no_more, sW1);
    kA<<<G_ / 4, 128>>>(imr, pgr, nodes, focus, sW1, sb1, tW1, tb1, sW2, sb2, out);
    kB<<<N_ / 128, 512>>>(nodes, sW1, tW1, n2g);
    kE<<<1184, 256>>>(targets, (const float4*)feats, sW1, tW1, sW2, sb2, tW2, tb2,
                      dist_table, out);
}

// round 15
// speedup vs baseline: 1.0794x; 1.0202x over previous
#include <cuda_runtime.h>

#define G_   1024
#define N_   65536
#define D_   128
#define E_   400000

// Scratch (device globals — no allocations allowed)
__device__ __align__(16) float g_A[G_ * 128];      // graph_and_focus @ W1[0:384] + b1 (64 scorer | 64 type cols)
__device__ __align__(16) float g_C[N_ * 128];      // node @ W1[384:512] + A[n2g[node]] (fused per-node table)

// packed f32x2 helpers (full-rate FMA pipe; scalar 3-reg FFMA is half-rate)
__device__ __forceinline__ unsigned long long fma2(unsigned long long a, unsigned long long b,
                                                   unsigned long long c) {
    unsigned long long d;
    asm("fma.rn.f32x2 %0, %1, %2, %3;" : "=l"(d) : "l"(a), "l"(b), "l"(c));
    return d;
}
__device__ __forceinline__ unsigned long long pack2(float lo, float hi) {
    unsigned long long d;
    asm("mov.b64 %0, {%1, %2};" : "=l"(d) : "f"(lo), "f"(hi));
    return d;
}
__device__ __forceinline__ void unpack2(unsigned long long v, float& lo, float& hi) {
    asm("mov.b64 {%0, %1}, %2;" : "=f"(lo), "=f"(hi) : "l"(v));
}

// ---------------------------------------------------------------------------
// kA: pure GEMM. A[g][j] = [imr|pgr|focus] @ W1[0:384] + b1.
//     4 graphs/block x 256 blocks (stop logits moved to kB tail blocks).
// ---------------------------------------------------------------------------
__global__ void kA(const float* __restrict__ imr, const float* __restrict__ pgr,
                   const float* __restrict__ nodes, const int* __restrict__ focus,
                   const float* __restrict__ sW1, const float* __restrict__ sb1,
                   const float* __restrict__ tW1, const float* __restrict__ tb1) {
    __shared__ float xs[4][384];
    int j = threadIdx.x;
    int g0 = blockIdx.x * 4;
#pragma unroll
    for (int r = 0; r < 4; r++) {
        int g = g0 + r;
        xs[r][j]       = imr[g * 128 + j];
        xs[r][128 + j] = pgr[g * 128 + j];
        xs[r][256 + j] = nodes[(size_t)focus[g] * 128 + j];
    }
    __syncthreads();
    bool isS = (j < 64);
    float bias = isS ? sb1[j] : tb1[j - 64];
    const float* W = isS ? (sW1 + j) : (tW1 + (j - 64));
    float acc[4];
#pragma unroll
    for (int r = 0; r < 4; r++) acc[r] = bias;
#pragma unroll 8
    for (int k = 0; k < 384; k++) {
        float w = W[k * 64];
#pragma unroll
        for (int r = 0; r < 4; r++) acc[r] = fmaf(xs[r][k], w, acc[r]);
    }
#pragma unroll
    for (int r = 0; r < 4; r++) g_A[(size_t)(g0 + r) * 128 + j] = acc[r];
}

// ---------------------------------------------------------------------------
// kB: blocks 0-511: C[n][j] = node[n] @ W1comb[384:512] + A[n2g[n]][j]
//     (R9 v2 GEMM path, measured ~75us, byte-identical).
//     blocks 512-515: cstop + stop logits (runs concurrently on 4 SMs,
//     cost hidden inside the GEMM blocks' runtime).
// ---------------------------------------------------------------------------
__global__ __launch_bounds__(512, 2) void kB(const float* __restrict__ nodes,
                                             const float* __restrict__ sW1,
                                             const float* __restrict__ tW1,
                                             const int* __restrict__ n2g,
                                             const float* __restrict__ no_more,
                                             const float* __restrict__ sW2,
                                             const float* __restrict__ sb2,
                                             float* __restrict__ out) {
    __shared__ float xs[32][132];   // [k][r] transposed, padded
    __shared__ float sw[32][128];   // [k][j] combined cols
    int tid = threadIdx.x;

    if (blockIdx.x >= 512) {
        // ---- tail block: cstop + stop logits for 256 graphs ----
        __shared__ float part[4][64];
        __shared__ float cst[64];
        int b = blockIdx.x - 512;
        if (tid < 256) {
            int j = tid & 63, s = tid >> 6;   // 4 K-slices of 33 (4*33 = 132)
            float sum = 0.f;
#pragma unroll 3
            for (int k = s * 33; k < s * 33 + 33; k++)
                sum += no_more[k] * sW1[(384 + k) * 64 + j];
            part[s][j] = sum;
        }
        __syncthreads();
        if (tid < 64)
            cst[tid] = part[0][tid] + part[1][tid] + part[2][tid] + part[3][tid];
        __syncthreads();
        int lane = tid & 31, wid = tid >> 5;     // 16 warps
        float ws0 = sW2[lane], ws1 = sW2[32 + lane];
        float c0v = cst[lane], c1v = cst[32 + lane];
        float sb = sb2[0];
        for (int i = 0; i < 16; i++) {
            int g = b * 256 + i * 16 + wid;
            float a0 = g_A[(size_t)g * 128 + lane];
            float a1 = g_A[(size_t)g * 128 + 32 + lane];
            float v = fmaxf(a0 + c0v, 0.f) * ws0 + fmaxf(a1 + c1v, 0.f) * ws1;
#pragma unroll
            for (int o = 16; o >= 1; o >>= 1) v += __shfl_xor_sync(0xffffffffu, v, o);
            if (lane == 0) out[E_ + g] = v + sb;
        }
        return;
    }

    // ---- GEMM blocks (unchanged from measured-best) ----
    int tx = tid & 31, ty = tid >> 5;
    int c0 = tx * 4, r0 = ty * 8;
    int row0 = blockIdx.x * 128;

    unsigned long long acc[4][4];   // [row-pair][col]
#pragma unroll
    for (int i = 0; i < 4; i++)
#pragma unroll
        for (int j = 0; j < 4; j++) acc[i][j] = 0ull;

    for (int kc = 0; kc < 128; kc += 32) {
        for (int i = tid; i < 32 * 128; i += 512) {
            int k = i >> 7, j = i & 127;
            sw[k][j] = (j < 64) ? sW1[(384 + kc + k) * 64 + j]
                                : tW1[(384 + kc + k) * 64 + (j - 64)];
        }
        for (int f = tid; f < 1024; f += 512) {
            int r = f >> 3, kq = (f & 7) << 2;
            float4 v = *(const float4*)(nodes + (size_t)(row0 + r) * 128 + kc + kq);
            xs[kq + 0][r] = v.x; xs[kq + 1][r] = v.y;
            xs[kq + 2][r] = v.z; xs[kq + 3][r] = v.w;
        }
        __syncthreads();
#pragma unroll 8
        for (int k = 0; k < 32; k++) {
            const unsigned long long* xp = (const unsigned long long*)&xs[k][r0];
            unsigned long long x0 = xp[0], x1 = xp[1], x2 = xp[2], x3 = xp[3];
            float4 w = *(const float4*)&sw[k][c0];
            unsigned long long w0 = pack2(w.x, w.x), w1 = pack2(w.y, w.y);
            unsigned long long w2 = pack2(w.z, w.z), w3 = pack2(w.w, w.w);
            acc[0][0] = fma2(x0, w0, acc[0][0]); acc[0][1] = fma2(x0, w1, acc[0][1]);
            acc[0][2] = fma2(x0, w2, acc[0][2]); acc[0][3] = fma2(x0, w3, acc[0][3]);
            acc[1][0] = fma2(x1, w0, acc[1][0]); acc[1][1] = fma2(x1, w1, acc[1][1]);
            acc[1][2] = fma2(x1, w2, acc[1][2]); acc[1][3] = fma2(x1, w3, acc[1][3]);
            acc[2][0] = fma2(x2, w0, acc[2][0]); acc[2][1] = fma2(x2, w1, acc[2][1]);
            acc[2][2] = fma2(x2, w2, acc[2][2]); acc[2][3] = fma2(x2, w3, acc[2][3]);
            acc[3][0] = fma2(x3, w0, acc[3][0]); acc[3][1] = fma2(x3, w1, acc[3][1]);
            acc[3][2] = fma2(x3, w2, acc[3][2]); acc[3][3] = fma2(x3, w3, acc[3][3]);
        }
        __syncthreads();
    }
    // epilogue: unpack, add A[n2g[row]] (n2g sorted -> near-sequential), store
#pragma unroll
    for (int i = 0; i < 4; i++) {
        float lo[4], hi[4];
#pragma unroll
        for (int j = 0; j < 4; j++) unpack2(acc[i][j], lo[j], hi[j]);
        int rowA = row0 + r0 + 2 * i;
        int gA = n2g[rowA], gB = n2g[rowA + 1];
        float4 a0 = *(const float4*)(g_A + (size_t)gA * 128 + c0);
        float4 b0 = *(const float4*)(g_A + (size_t)gB * 128 + c0);
        *(float4*)(g_C + (size_t)rowA * 128 + c0) =
            make_float4(lo[0] + a0.x, lo[1] + a0.y, lo[2] + a0.z, lo[3] + a0.w);
        *(float4*)(g_C + (size_t)(rowA + 1) * 128 + c0) =
            make_float4(hi[0] + b0.x, hi[1] + b0.y, hi[2] + b0.z, hi[3] + b0.w);
    }
}

// ---------------------------------------------------------------------------
// kE (R8/R9 exact, measured 74.0-74.8us three times): 1 edge per warp, lane
//     owns 4 combined cols via float4 gather; scalar 4-chain FMA h; scalar
//     dist; 1-deep prefetch of targets->C chain. DO NOT TOUCH.
// ---------------------------------------------------------------------------
__global__ __launch_bounds__(256) void kE(const int* __restrict__ targets,
                   const float4* __restrict__ feats4,
                   const float* __restrict__ sW1, const float* __restrict__ tW1,
                   const float* __restrict__ sW2, const float* __restrict__ sb2,
                   const float* __restrict__ tW2, const float* __restrict__ tb2,
                   const float* __restrict__ dist_table,
                   float* __restrict__ out) {
    __shared__ float sdt[10];
    if (threadIdx.x < 10) sdt[threadIdx.x] = dist_table[threadIdx.x];
    __syncthreads();

    int lane = threadIdx.x & 31;
    bool isS = (lane < 16);
    int cbase = (lane & 15) * 4;
    const float* W1 = isS ? sW1 : tW1;
    float4 w512 = *(const float4*)(W1 + 512 * 64 + cbase);
    float4 w513 = *(const float4*)(W1 + 513 * 64 + cbase);
    float4 w514 = *(const float4*)(W1 + 514 * 64 + cbase);
    float4 w515 = *(const float4*)(W1 + 515 * 64 + cbase);
    float4 u0, u1, u2;
    if (isS) {
        u0 = *(const float4*)(sW2 + cbase);
        u1 = make_float4(0.f, 0.f, 0.f, 0.f);
        u2 = u1;
    } else {
        u0.x = tW2[(cbase + 0) * 3]; u0.y = tW2[(cbase + 1) * 3];
        u0.z = tW2[(cbase + 2) * 3]; u0.w = tW2[(cbase + 3) * 3];
        u1.x = tW2[(cbase + 0) * 3 + 1]; u1.y = tW2[(cbase + 1) * 3 + 1];
        u1.z = tW2[(cbase + 2) * 3 + 1]; u1.w = tW2[(cbase + 3) * 3 + 1];
        u2.x = tW2[(cbase + 0) * 3 + 2]; u2.y = tW2[(cbase + 1) * 3 + 2];
        u2.z = tW2[(cbase + 2) * 3 + 2]; u2.w = tW2[(cbase + 3) * 3 + 2];
    }
    float sb2v = sb2[0];
    float tb0 = tb2[0], tb1v = tb2[1], tb2v = tb2[2];
    const float4* C4 = (const float4*)g_C;
    float* outT = out + (E_ + G_);

    int gw = (blockIdx.x * blockDim.x + threadIdx.x) >> 5;
    int nw = (gridDim.x * blockDim.x) >> 5;

    int e = gw;
    float4 f, c;
    if (e < E_) {
        int t = targets[e];
        f = feats4[e];
        c = C4[(size_t)t * 32 + lane];
    }
    while (e < E_) {
        int e2 = e + nw;
        float4 f2, c2;
        if (e2 < E_) {
            int t2 = targets[e2];
            f2 = feats4[e2];
            c2 = C4[(size_t)t2 * 32 + lane];
        }
        float dv = sdt[(int)fminf(f.x, 9.0f)];
        float hx = fmaxf(fmaf(dv, w512.x, fmaf(f.y, w513.x, fmaf(f.z, w514.x, fmaf(f.w, w515.x, c.x)))), 0.f);
        float hy = fmaxf(fmaf(dv, w512.y, fmaf(f.y, w513.y, fmaf(f.z, w514.y, fmaf(f.w, w515.y, c.y)))), 0.f);
        float hz = fmaxf(fmaf(dv, w512.z, fmaf(f.y, w513.z, fmaf(f.z, w514.z, fmaf(f.w, w515.z, c.z)))), 0.f);
        float hw = fmaxf(fmaf(dv, w512.w, fmaf(f.y, w513.w, fmaf(f.z, w514.w, fmaf(f.w, w515.w, c.w)))), 0.f);
        float v0 = fmaf(hx, u0.x, fmaf(hy, u0.y, fmaf(hz, u0.z, hw * u0.w)));
        float v1 = fmaf(hx, u1.x, fmaf(hy, u1.y, fmaf(hz, u1.z, hw * u1.w)));
        float v2 = fmaf(hx, u2.x, fmaf(hy, u2.y, fmaf(hz, u2.z, hw * u2.w)));
        float p = isS ? v0 : v1;
        float q = __shfl_xor_sync(0xffffffffu, v0, 16);
        q = isS ? q : v2;
#pragma unroll
        for (int o = 1; o <= 8; o <<= 1) {
            p += __shfl_xor_sync(0xffffffffu, p, o);
            q += __shfl_xor_sync(0xffffffffu, q, o);
        }
        if (lane == 0) {
            out[e] = p + sb2v;          // scorer logit
            outT[3 * e] = q + tb0;      // type logit 0
        }
        if (lane == 16) {
            outT[3 * e + 1] = p + tb1v; // type logit 1
            outT[3 * e + 2] = q + tb2v; // type logit 2
        }
        e = e2; f = f2; c = c2;
    }
}

// ---------------------------------------------------------------------------
extern "C" void kernel_launch(void* const* d_in, const int* in_sizes, int n_in,
                              void* d_out, int out_size) {
    const float* imr     = (const float*)d_in[0];
    const float* pgr     = (const float*)d_in[1];
    const float* nodes   = (const float*)d_in[2];
    const int*   focus   = (const int*)d_in[3];
    const int*   n2g     = (const int*)d_in[4];
    const int*   targets = (const int*)d_in[5];
    const float* feats   = (const float*)d_in[6];
    int p = 7;
    if (p < n_in && in_sizes[p] == 1) p++;  // skip num_graphs_in_batch scalar if present
    const float* dist_table = (const float*)d_in[p++];  // [10]
    const float* no_more    = (const float*)d_in[p++];  // [132]
    const float* sW1 = (const float*)d_in[p++];         // [516,64]
    const float* sb1 = (const float*)d_in[p++];         // [64]
    const float* sW2 = (const float*)d_in[p++];         // [64]
    const float* sb2 = (const float*)d_in[p++];         // [1]
    const float* tW1 = (const float*)d_in[p++];         // [516,64]
    const float* tb1 = (const float*)d_in[p++];         // [64]
    const float* tW2 = (const float*)d_in[p++];         // [64,3]
    const float* tb2 = (const float*)d_in[p++];         // [3]
    float* out = (float*)d_out;

    kA<<<G_ / 4, 128>>>(imr, pgr, nodes, focus, sW1, sb1, tW1, tb1);
    kB<<<N_ / 128 + 4, 512>>>(nodes, sW1, tW1, n2g, no_more, sW2, sb2, out);
    kE<<<1184, 256>>>(targets, (const float4*)feats, sW1, tW1, sW2, sb2, tW2, tb2,
                      dist_table, out);
}

// round 16
// speedup vs baseline: 1.2367x; 1.1458x over previous
#include <cuda_runtime.h>

#define G_   1024
#define N_   65536
#define D_   128
#define E_   400000

// Scratch (device globals — no allocations allowed)
__device__ __align__(16) float g_A[G_ * 128];        // assembled A (64 scorer | 64 type cols)
__device__ __align__(16) float g_Apart[4 * G_ * 128]; // K-slice partials
__device__ __align__(16) float g_C[N_ * 128];        // node @ W1[384:512] + A[n2g[node]]

// packed f32x2 helpers (full-rate FMA pipe; scalar 3-reg FFMA is half-rate)
__device__ __forceinline__ unsigned long long fma2(unsigned long long a, unsigned long long b,
                                                   unsigned long long c) {
    unsigned long long d;
    asm("fma.rn.f32x2 %0, %1, %2, %3;" : "=l"(d) : "l"(a), "l"(b), "l"(c));
    return d;
}
__device__ __forceinline__ unsigned long long pack2(float lo, float hi) {
    unsigned long long d;
    asm("mov.b64 %0, {%1, %2};" : "=l"(d) : "f"(lo), "f"(hi));
    return d;
}
__device__ __forceinline__ void unpack2(unsigned long long v, float& lo, float& hi) {
    asm("mov.b64 {%0, %1}, %2;" : "=f"(lo), "=f"(hi) : "l"(v));
}

// ---------------------------------------------------------------------------
// kA v4: K-split GEMM partials. grid (256, 4): blockIdx.x = 4-graph group,
//     blockIdx.y = 96-wide K slice. 1024 blocks x 4 warps = 4x the warps and
//     1/4 the serial chain of the 43us v3.
// ---------------------------------------------------------------------------
__global__ void kA(const float* __restrict__ imr, const float* __restrict__ pgr,
                   const float* __restrict__ nodes, const int* __restrict__ focus,
                   const float* __restrict__ sW1, const float* __restrict__ tW1) {
    __shared__ float xs[4][96];
    __shared__ int foc[4];
    int j = threadIdx.x;                // 0..127 = combined hidden col
    int g0 = blockIdx.x * 4;
    int s = blockIdx.y;                 // 0..3
    int kbase = s * 96;
    if (j < 4) foc[j] = focus[g0 + j];
    __syncthreads();
    for (int idx = j; idx < 4 * 96; idx += 128) {
        int r = idx / 96, kk = idx - r * 96;
        int kg = kbase + kk;
        float v;
        if (kg < 128)      v = imr[(size_t)(g0 + r) * 128 + kg];
        else if (kg < 256) v = pgr[(size_t)(g0 + r) * 128 + (kg - 128)];
        else               v = nodes[(size_t)foc[r] * 128 + (kg - 256)];
        xs[r][kk] = v;
    }
    __syncthreads();
    bool isS = (j < 64);
    const float* W = (isS ? (sW1 + j) : (tW1 + (j - 64))) + (size_t)kbase * 64;
    float a0 = 0.f, a1 = 0.f, a2 = 0.f, a3 = 0.f;
#pragma unroll 8
    for (int k = 0; k < 96; k++) {
        float w = W[k * 64];
        a0 = fmaf(xs[0][k], w, a0);
        a1 = fmaf(xs[1][k], w, a1);
        a2 = fmaf(xs[2][k], w, a2);
        a3 = fmaf(xs[3][k], w, a3);
    }
    float* o = g_Apart + (size_t)s * (G_ * 128) + (size_t)g0 * 128 + j;
    o[0] = a0; o[128] = a1; o[256] = a2; o[384] = a3;
}

// ---------------------------------------------------------------------------
// kR: g_A = bias + sum of 4 K-slice partials. 512 blocks x 256 threads.
// ---------------------------------------------------------------------------
__global__ void kR(const float* __restrict__ sb1, const float* __restrict__ tb1) {
    int i = blockIdx.x * 256 + threadIdx.x;     // 0..131071
    int j = i & 127;
    float b = (j < 64) ? sb1[j] : tb1[j - 64];
    g_A[i] = b + g_Apart[i] + g_Apart[G_ * 128 + i]
               + g_Apart[2 * G_ * 128 + i] + g_Apart[3 * G_ * 128 + i];
}

// ---------------------------------------------------------------------------
// kB: blocks 0-511: C[n][j] = node[n] @ W1comb[384:512] + A[n2g[n]][j]
//     (measured-best GEMM path). blocks 512-515: cstop + stop logits
//     (hidden on 4 SMs inside the GEMM runtime).
// ---------------------------------------------------------------------------
__global__ __launch_bounds__(512, 2) void kB(const float* __restrict__ nodes,
                                             const float* __restrict__ sW1,
                                             const float* __restrict__ tW1,
                                             const int* __restrict__ n2g,
                                             const float* __restrict__ no_more,
                                             const float* __restrict__ sW2,
                                             const float* __restrict__ sb2,
                                             float* __restrict__ out) {
    __shared__ float xs[32][132];   // [k][r] transposed, padded
    __shared__ float sw[32][128];   // [k][j] combined cols
    int tid = threadIdx.x;

    if (blockIdx.x >= 512) {
        // ---- tail block: cstop + stop logits for 256 graphs ----
        __shared__ float part[4][64];
        __shared__ float cst[64];
        int b = blockIdx.x - 512;
        if (tid < 256) {
            int j = tid & 63, s = tid >> 6;   // 4 K-slices of 33 (4*33 = 132)
            float sum = 0.f;
#pragma unroll 3
            for (int k = s * 33; k < s * 33 + 33; k++)
                sum += no_more[k] * sW1[(384 + k) * 64 + j];
            part[s][j] = sum;
        }
        __syncthreads();
        if (tid < 64)
            cst[tid] = part[0][tid] + part[1][tid] + part[2][tid] + part[3][tid];
        __syncthreads();
        int lane = tid & 31, wid = tid >> 5;     // 16 warps
        float ws0 = sW2[lane], ws1 = sW2[32 + lane];
        float c0v = cst[lane], c1v = cst[32 + lane];
        float sb = sb2[0];
        for (int i = 0; i < 16; i++) {
            int g = b * 256 + i * 16 + wid;
            float a0 = g_A[(size_t)g * 128 + lane];
            float a1 = g_A[(size_t)g * 128 + 32 + lane];
            float v = fmaxf(a0 + c0v, 0.f) * ws0 + fmaxf(a1 + c1v, 0.f) * ws1;
#pragma unroll
            for (int o = 16; o >= 1; o >>= 1) v += __shfl_xor_sync(0xffffffffu, v, o);
            if (lane == 0) out[E_ + g] = v + sb;
        }
        return;
    }

    // ---- GEMM blocks (unchanged from measured-best) ----
    int tx = tid & 31, ty = tid >> 5;
    int c0 = tx * 4, r0 = ty * 8;
    int row0 = blockIdx.x * 128;

    unsigned long long acc[4][4];   // [row-pair][col]
#pragma unroll
    for (int i = 0; i < 4; i++)
#pragma unroll
        for (int j = 0; j < 4; j++) acc[i][j] = 0ull;

    for (int kc = 0; kc < 128; kc += 32) {
        for (int i = tid; i < 32 * 128; i += 512) {
            int k = i >> 7, j = i & 127;
            sw[k][j] = (j < 64) ? sW1[(384 + kc + k) * 64 + j]
                                : tW1[(384 + kc + k) * 64 + (j - 64)];
        }
        for (int f = tid; f < 1024; f += 512) {
            int r = f >> 3, kq = (f & 7) << 2;
            float4 v = *(const float4*)(nodes + (size_t)(row0 + r) * 128 + kc + kq);
            xs[kq + 0][r] = v.x; xs[kq + 1][r] = v.y;
            xs[kq + 2][r] = v.z; xs[kq + 3][r] = v.w;
        }
        __syncthreads();
#pragma unroll 8
        for (int k = 0; k < 32; k++) {
            const unsigned long long* xp = (const unsigned long long*)&xs[k][r0];
            unsigned long long x0 = xp[0], x1 = xp[1], x2 = xp[2], x3 = xp[3];
            float4 w = *(const float4*)&sw[k][c0];
            unsigned long long w0 = pack2(w.x, w.x), w1 = pack2(w.y, w.y);
            unsigned long long w2 = pack2(w.z, w.z), w3 = pack2(w.w, w.w);
            acc[0][0] = fma2(x0, w0, acc[0][0]); acc[0][1] = fma2(x0, w1, acc[0][1]);
            acc[0][2] = fma2(x0, w2, acc[0][2]); acc[0][3] = fma2(x0, w3, acc[0][3]);
            acc[1][0] = fma2(x1, w0, acc[1][0]); acc[1][1] = fma2(x1, w1, acc[1][1]);
            acc[1][2] = fma2(x1, w2, acc[1][2]); acc[1][3] = fma2(x1, w3, acc[1][3]);
            acc[2][0] = fma2(x2, w0, acc[2][0]); acc[2][1] = fma2(x2, w1, acc[2][1]);
            acc[2][2] = fma2(x2, w2, acc[2][2]); acc[2][3] = fma2(x2, w3, acc[2][3]);
            acc[3][0] = fma2(x3, w0, acc[3][0]); acc[3][1] = fma2(x3, w1, acc[3][1]);
            acc[3][2] = fma2(x3, w2, acc[3][2]); acc[3][3] = fma2(x3, w3, acc[3][3]);
        }
        __syncthreads();
    }
    // epilogue: unpack, add A[n2g[row]] (n2g sorted -> near-sequential), store
#pragma unroll
    for (int i = 0; i < 4; i++) {
        float lo[4], hi[4];
#pragma unroll
        for (int j = 0; j < 4; j++) unpack2(acc[i][j], lo[j], hi[j]);
        int rowA = row0 + r0 + 2 * i;
        int gA = n2g[rowA], gB = n2g[rowA + 1];
        float4 a0 = *(const float4*)(g_A + (size_t)gA * 128 + c0);
        float4 b0 = *(const float4*)(g_A + (size_t)gB * 128 + c0);
        *(float4*)(g_C + (size_t)rowA * 128 + c0) =
            make_float4(lo[0] + a0.x, lo[1] + a0.y, lo[2] + a0.z, lo[3] + a0.w);
        *(float4*)(g_C + (size_t)(rowA + 1) * 128 + c0) =
            make_float4(hi[0] + b0.x, hi[1] + b0.y, hi[2] + b0.z, hi[3] + b0.w);
    }
}

// ---------------------------------------------------------------------------
// kE (measured 74.0-74.8us three times): 1 edge per warp, lane owns 4
//     combined cols via float4 gather; scalar 4-chain FMA h; scalar dist;
//     1-deep prefetch of targets->C chain. DO NOT TOUCH.
// ---------------------------------------------------------------------------
__global__ __launch_bounds__(256) void kE(const int* __restrict__ targets,
                   const float4* __restrict__ feats4,
                   const float* __restrict__ sW1, const float* __restrict__ tW1,
                   const float* __restrict__ sW2, const float* __restrict__ sb2,
                   const float* __restrict__ tW2, const float* __restrict__ tb2,
                   const float* __restrict__ dist_table,
                   float* __restrict__ out) {
    __shared__ float sdt[10];
    if (threadIdx.x < 10) sdt[threadIdx.x] = dist_table[threadIdx.x];
    __syncthreads();

    int lane = threadIdx.x & 31;
    bool isS = (lane < 16);
    int cbase = (lane & 15) * 4;
    const float* W1 = isS ? sW1 : tW1;
    float4 w512 = *(const float4*)(W1 + 512 * 64 + cbase);
    float4 w513 = *(const float4*)(W1 + 513 * 64 + cbase);
    float4 w514 = *(const float4*)(W1 + 514 * 64 + cbase);
    float4 w515 = *(const float4*)(W1 + 515 * 64 + cbase);
    float4 u0, u1, u2;
    if (isS) {
        u0 = *(const float4*)(sW2 + cbase);
        u1 = make_float4(0.f, 0.f, 0.f, 0.f);
        u2 = u1;
    } else {
        u0.x = tW2[(cbase + 0) * 3]; u0.y = tW2[(cbase + 1) * 3];
        u0.z = tW2[(cbase + 2) * 3]; u0.w = tW2[(cbase + 3) * 3];
        u1.x = tW2[(cbase + 0) * 3 + 1]; u1.y = tW2[(cbase + 1) * 3 + 1];
        u1.z = tW2[(cbase + 2) * 3 + 1]; u1.w = tW2[(cbase + 3) * 3 + 1];
        u2.x = tW2[(cbase + 0) * 3 + 2]; u2.y = tW2[(cbase + 1) * 3 + 2];
        u2.z = tW2[(cbase + 2) * 3 + 2]; u2.w = tW2[(cbase + 3) * 3 + 2];
    }
    float sb2v = sb2[0];
    float tb0 = tb2[0], tb1v = tb2[1], tb2v = tb2[2];
    const float4* C4 = (const float4*)g_C;
    float* outT = out + (E_ + G_);

    int gw = (blockIdx.x * blockDim.x + threadIdx.x) >> 5;
    int nw = (gridDim.x * blockDim.x) >> 5;

    int e = gw;
    float4 f, c;
    if (e < E_) {
        int t = targets[e];
        f = feats4[e];
        c = C4[(size_t)t * 32 + lane];
    }
    while (e < E_) {
        int e2 = e + nw;
        float4 f2, c2;
        if (e2 < E_) {
            int t2 = targets[e2];
            f2 = feats4[e2];
            c2 = C4[(size_t)t2 * 32 + lane];
        }
        float dv = sdt[(int)fminf(f.x, 9.0f)];
        float hx = fmaxf(fmaf(dv, w512.x, fmaf(f.y, w513.x, fmaf(f.z, w514.x, fmaf(f.w, w515.x, c.x)))), 0.f);
        float hy = fmaxf(fmaf(dv, w512.y, fmaf(f.y, w513.y, fmaf(f.z, w514.y, fmaf(f.w, w515.y, c.y)))), 0.f);
        float hz = fmaxf(fmaf(dv, w512.z, fmaf(f.y, w513.z, fmaf(f.z, w514.z, fmaf(f.w, w515.z, c.z)))), 0.f);
        float hw = fmaxf(fmaf(dv, w512.w, fmaf(f.y, w513.w, fmaf(f.z, w514.w, fmaf(f.w, w515.w, c.w)))), 0.f);
        float v0 = fmaf(hx, u0.x, fmaf(hy, u0.y, fmaf(hz, u0.z, hw * u0.w)));
        float v1 = fmaf(hx, u1.x, fmaf(hy, u1.y, fmaf(hz, u1.z, hw * u1.w)));
        float v2 = fmaf(hx, u2.x, fmaf(hy, u2.y, fmaf(hz, u2.z, hw * u2.w)));
        float p = isS ? v0 : v1;
        float q = __shfl_xor_sync(0xffffffffu, v0, 16);
        q = isS ? q : v2;
#pragma unroll
        for (int o = 1; o <= 8; o <<= 1) {
            p += __shfl_xor_sync(0xffffffffu, p, o);
            q += __shfl_xor_sync(0xffffffffu, q, o);
        }
        if (lane == 0) {
            out[e] = p + sb2v;          // scorer logit
            outT[3 * e] = q + tb0;      // type logit 0
        }
        if (lane == 16) {
            outT[3 * e + 1] = p + tb1v; // type logit 1
            outT[3 * e + 2] = q + tb2v; // type logit 2
        }
        e = e2; f = f2; c = c2;
    }
}

// ---------------------------------------------------------------------------
extern "C" void kernel_launch(void* const* d_in, const int* in_sizes, int n_in,
                              void* d_out, int out_size) {
    const float* imr     = (const float*)d_in[0];
    const float* pgr     = (const float*)d_in[1];
    const float* nodes   = (const float*)d_in[2];
    const int*   focus   = (const int*)d_in[3];
    const int*   n2g     = (const int*)d_in[4];
    const int*   targets = (const int*)d_in[5];
    const float* feats   = (const float*)d_in[6];
    int p = 7;
    if (p < n_in && in_sizes[p] == 1) p++;  // skip num_graphs_in_batch scalar if present
    const float* dist_table = (const float*)d_in[p++];  // [10]
    const float* no_more    = (const float*)d_in[p++];  // [132]
    const float* sW1 = (const float*)d_in[p++];         // [516,64]
    const float* sb1 = (const float*)d_in[p++];         // [64]
    const float* sW2 = (const float*)d_in[p++];         // [64]
    const float* sb2 = (const float*)d_in[p++];         // [1]
    const float* tW1 = (const float*)d_in[p++];         // [516,64]
    const float* tb1 = (const float*)d_in[p++];         // [64]
    const float* tW2 = (const float*)d_in[p++];         // [64,3]
    const float* tb2 = (const float*)d_in[p++];         // [3]
    float* out = (float*)d_out;

    kA<<<dim3(G_ / 4, 4), 128>>>(imr, pgr, nodes, focus, sW1, tW1);
    kR<<<G_ * 128 / 256, 256>>>(sb1, tb1);
    kB<<<N_ / 128 + 4, 512>>>(nodes, sW1, tW1, n2g, no_more, sW2, sb2, out);
    kE<<<1184, 256>>>(targets, (const float4*)feats, sW1, tW1, sW2, sb2, tW2, tb2,
                      dist_table, out);
}